// round 12
// baseline (speedup 1.0000x reference)
#include <cuda_runtime.h>
#include <cuda_fp16.h>
#include <math.h>
#include <stdint.h>

#define D 768
#define E 8
#define F 3072
#define T_TOK 4096
#define MAXROWS 10240

typedef __half f16;

__device__ int   g_counts[E];
__device__ int   g_off[E + 1];
__device__ int   g_list[E * T_TOK];
__device__ float g_gates[E * T_TOK];
__device__ f16   g_A[(size_t)MAXROWS * D];
__device__ f16   g_H[(size_t)MAXROWS * F];
__device__ f16   g_W1[(size_t)E * D * F];   // [E][D][F] native [k][n], fp16
__device__ f16   g_W2[(size_t)E * D * F];   // [E][F][D] native [k][n], fp16

__device__ __forceinline__ uint32_t smem_u32(const void* p) {
    uint32_t a;
    asm("{ .reg .u64 t; cvta.to.shared.u64 t, %1; cvt.u32.u64 %0, t; }" : "=r"(a) : "l"(p));
    return a;
}
__device__ __forceinline__ void cp16(uint32_t dst, const void* src) {
    asm volatile("cp.async.cg.shared.global [%0], [%1], 16;"
                 :: "r"(dst), "l"(__cvta_generic_to_global(src)));
}
#define CP_COMMIT() asm volatile("cp.async.commit_group;" ::: "memory")

__device__ __forceinline__ void ldm_x4(uint32_t* r, uint32_t addr) {
    asm volatile("ldmatrix.sync.aligned.m8n8.x4.shared.b16 {%0,%1,%2,%3}, [%4];"
                 : "=r"(r[0]), "=r"(r[1]), "=r"(r[2]), "=r"(r[3]) : "r"(addr));
}
__device__ __forceinline__ void ldm_x4_t(uint32_t* r, uint32_t addr) {
    asm volatile("ldmatrix.sync.aligned.m8n8.x4.trans.shared.b16 {%0,%1,%2,%3}, [%4];"
                 : "=r"(r[0]), "=r"(r[1]), "=r"(r[2]), "=r"(r[3]) : "r"(addr));
}
__device__ __forceinline__ void mma_f16(float* c, const uint32_t* a, uint32_t b0, uint32_t b1) {
    asm volatile("mma.sync.aligned.m16n8k16.row.col.f32.f16.f16.f32 "
                 "{%0,%1,%2,%3}, {%4,%5,%6,%7}, {%8,%9}, {%0,%1,%2,%3};"
                 : "+f"(c[0]), "+f"(c[1]), "+f"(c[2]), "+f"(c[3])
                 : "r"(a[0]), "r"(a[1]), "r"(a[2]), "r"(a[3]), "r"(b0), "r"(b1));
}

__global__ void init_kernel() { if (threadIdx.x < E) g_counts[threadIdx.x] = 0; }

// warp-per-token router: 8 tokens per 256-thread block, Wg/Wn staged transposed in smem.
#define WPITCH 776
__global__ void __launch_bounds__(256) router_kernel(
        const float* __restrict__ x, const float* __restrict__ noise,
        const float* __restrict__ Wg, const float* __restrict__ bg,
        const float* __restrict__ Wn, const float* __restrict__ bn) {
    __shared__ float wg[E * WPITCH];
    __shared__ float wn[E * WPITCH];
    int tid = threadIdx.x, lane = tid & 31, w = tid >> 5;
    for (int i = tid; i < D * E; i += 256) {
        int d = i >> 3, e = i & 7;
        wg[e * WPITCH + d] = Wg[i];
        wn[e * WPITCH + d] = Wn[i];
    }
    __syncthreads();

    int t = blockIdx.x * 8 + w;
    const float* xr = x + (size_t)t * D;
    float xv[D / 32];
    #pragma unroll
    for (int i = 0; i < D / 32; i++) xv[i] = xr[i * 32 + lane];

    float sg[E], sn[E];
    #pragma unroll
    for (int e = 0; e < E; e++) { sg[e] = 0.f; sn[e] = 0.f; }
    #pragma unroll
    for (int i = 0; i < D / 32; i++) {
        int d = i * 32 + lane;
        #pragma unroll
        for (int e = 0; e < E; e++) {
            sg[e] = fmaf(xv[i], wg[e * WPITCH + d], sg[e]);
            sn[e] = fmaf(xv[i], wn[e * WPITCH + d], sn[e]);
        }
    }
    #pragma unroll
    for (int e = 0; e < E; e++) {
        #pragma unroll
        for (int o = 16; o > 0; o >>= 1) {
            sg[e] += __shfl_xor_sync(~0u, sg[e], o);
            sn[e] += __shfl_xor_sync(~0u, sn[e], o);
        }
    }
    if (lane == 0) {
        float noisy[E];
        #pragma unroll
        for (int e = 0; e < E; e++) {
            float lg = sg[e] + bg[e], ln = sn[e] + bn[e];
            float sp = (ln > 20.f) ? ln : log1pf(expf(ln));
            noisy[e] = lg + noise[(size_t)t * E + e] * sp;
        }
        int i1 = 0; float v1 = noisy[0];
        #pragma unroll
        for (int e = 1; e < E; e++) if (noisy[e] > v1) { v1 = noisy[e]; i1 = e; }
        int i2 = -1; float v2 = -3.4e38f;
        #pragma unroll
        for (int e = 0; e < E; e++) {
            if (e == i1) continue;
            if (noisy[e] > v2) { v2 = noisy[e]; i2 = e; }
        }
        float eb = expf(v2 - v1);
        float p1 = 1.f / (1.f + eb), p2 = eb / (1.f + eb);
        if (p1 > 1e-9f) {
            int pos = atomicAdd(&g_counts[i1], 1);
            g_list[i1 * T_TOK + pos] = t; g_gates[i1 * T_TOK + pos] = p1;
        }
        if (p2 > 1e-9f) {
            int pos = atomicAdd(&g_counts[i2], 1);
            g_list[i2 * T_TOK + pos] = t; g_gates[i2 * T_TOK + pos] = p2;
        }
    }
}

__global__ void finalize_kernel() {
    if (threadIdx.x == 0) {
        int off = 0;
        for (int e = 0; e < E; e++) { g_off[e] = off; off += (g_counts[e] + 127) & ~127; }
        g_off[E] = off;
    }
}

__global__ void __launch_bounds__(256) gather_kernel(const float* __restrict__ x) {
    int e = blockIdx.x;
    int cnt = g_counts[e], pad = (cnt + 127) & ~127;
    int rb = blockIdx.y * 16;
    if (rb >= pad) return;
    int base = g_off[e];
    const int Q = D / 4;
    for (int idx = threadIdx.x; idx < 16 * Q; idx += 256) {
        int m = rb + idx / Q, q = idx % Q;
        float4 v = make_float4(0.f, 0.f, 0.f, 0.f);
        if (m < cnt)
            v = *(const float4*)&x[(size_t)g_list[e * T_TOK + m] * D + q * 4];
        f16 h[4];
        h[0] = __float2half_rn(v.x);
        h[1] = __float2half_rn(v.y);
        h[2] = __float2half_rn(v.z);
        h[3] = __float2half_rn(v.w);
        *(uint2*)&g_A[(size_t)(base + m) * D + q * 4] = *(uint2*)h;
    }
}

__global__ void __launch_bounds__(256) conv_weights_kernel(const float* __restrict__ W, int which) {
    f16* Th = which ? g_W2 : g_W1;
    const size_t n4 = (size_t)E * D * F / 4;
    size_t stride = (size_t)gridDim.x * blockDim.x;
    for (size_t i = (size_t)blockIdx.x * blockDim.x + threadIdx.x; i < n4; i += stride) {
        float4 v = *(const float4*)&W[i * 4];
        f16 h[4];
        h[0] = __float2half_rn(v.x);
        h[1] = __float2half_rn(v.y);
        h[2] = __float2half_rn(v.z);
        h[3] = __float2half_rn(v.w);
        *(uint2*)&Th[i * 4] = *(uint2*)h;
    }
}

// ------------- pure fp16 mma.sync GEMM, optional split-K -------------
// CTA 128 x 128, K-step 64, 3 smem stages, 4 warps (2M x 2N, warp 64x64), 2 CTAs/SM.
#define A_PITCH 144
#define A_ARR   18432
#define B_PITCH 272
#define B_ARR   17408
#define STG     35840
#define SMEM_G  107520    // 3 stages

template<int KTOT, int NTOT, int EPI, int SPLITK>
__global__ void __launch_bounds__(128, 2) moe_gemm_mma(const float* __restrict__ bias,
                                                       float* __restrict__ out) {
    constexpr int KLOC = KTOT / SPLITK;
    constexpr int NK   = KLOC / 64;

    int e = blockIdx.z, cnt = g_counts[e];
    int m0 = blockIdx.y * 128;
    int pad = (cnt + 127) & ~127;
    if (m0 >= pad) return;
    int nt = blockIdx.x / SPLITK;
    int ks = blockIdx.x % SPLITK;
    int n0 = nt * 128, rowbase = g_off[e];
    int kbase = ks * KLOC;

    extern __shared__ __align__(1024) char smem[];
    uint32_t sb0 = smem_u32(smem);
    int tid = threadIdx.x, wid = tid >> 5, lane = tid & 31;
    int WM = (wid >> 1) * 64;
    int WN = (wid & 1) * 64;

    const f16* Ag = (EPI == 1 ? g_A : g_H) + (size_t)(rowbase + m0) * KTOT + kbase;
    const f16* Bg = (EPI == 1 ? g_W1 : g_W2) + (size_t)e * D * F + (size_t)kbase * NTOT + n0;

    auto load_stage = [&](int s, int k0) {
        uint32_t sb = sb0 + s * STG;
        #pragma unroll
        for (int i = 0; i < 16; i++) {
            int c = tid + i * 128;
            if (c < 1024) {            // A: 128 rows x 8 chunks of 16B
                int row = c >> 3, ch = c & 7;
                cp16(sb + row * A_PITCH + ch * 16,
                     Ag + (size_t)row * KTOT + k0 + ch * 8);
            } else {                   // B: 64 k-rows x 16 chunks of 16B
                int cb = c - 1024, row = cb >> 4, ch = cb & 15;
                cp16(sb + A_ARR + row * B_PITCH + ch * 16,
                     Bg + (size_t)(k0 + row) * NTOT + ch * 8);
            }
        }
        CP_COMMIT();
    };

    float acc[4][8][4];
    #pragma unroll
    for (int mi = 0; mi < 4; mi++)
        #pragma unroll
        for (int ni = 0; ni < 8; ni++)
            #pragma unroll
            for (int q = 0; q < 4; q++) acc[mi][ni][q] = 0.f;

    uint32_t a_off = (uint32_t)((lane & 15) * A_PITCH + (lane >> 4) * 16);
    uint32_t b_off = (uint32_t)((lane & 15) * B_PITCH + (lane >> 4) * 16);

    load_stage(0, 0);
    load_stage(1, 64);

    for (int it = 0; it < NK; it++) {
        int s = it % 3;
        if (it + 1 < NK) asm volatile("cp.async.wait_group 1;" ::: "memory");
        else             asm volatile("cp.async.wait_group 0;" ::: "memory");
        __syncthreads();
        if (it + 2 < NK) load_stage((it + 2) % 3, (it + 2) * 64);

        uint32_t sA = sb0 + s * STG;
        uint32_t sB = sA + A_ARR;
        #pragma unroll
        for (int k16 = 0; k16 < 4; k16++) {
            uint32_t ah[4][4], bh[4][4];
            #pragma unroll
            for (int mi = 0; mi < 4; mi++)
                ldm_x4(ah[mi], sA + (WM + mi * 16) * A_PITCH + k16 * 32 + a_off);
            #pragma unroll
            for (int g = 0; g < 4; g++)
                ldm_x4_t(bh[g], sB + k16 * 16 * B_PITCH + (WN + g * 16) * 2 + b_off);
            #pragma unroll
            for (int mi = 0; mi < 4; mi++)
                #pragma unroll
                for (int g = 0; g < 4; g++) {
                    mma_f16(acc[mi][2 * g],     ah[mi], bh[g][0], bh[g][1]);
                    mma_f16(acc[mi][2 * g + 1], ah[mi], bh[g][2], bh[g][3]);
                }
        }
    }
    __syncthreads();

    // ---- epilogue via smem staging ----
    constexpr int EPITCH = 132;
    float* epi = (float*)smem;
    const float* bvec = bias + (size_t)e * NTOT + n0;
    float bscale = (ks == 0) ? 1.f : 0.f;
    int g4 = lane >> 2, t4 = lane & 3;
    #pragma unroll
    for (int mi = 0; mi < 4; mi++) {
        int r0 = WM + mi * 16 + g4;
        float gate0 = 0.f, gate8 = 0.f;
        if (EPI == 2) {
            if (m0 + r0 < cnt)     gate0 = g_gates[e * T_TOK + m0 + r0];
            if (m0 + r0 + 8 < cnt) gate8 = g_gates[e * T_TOK + m0 + r0 + 8];
        }
        #pragma unroll
        for (int ni = 0; ni < 8; ni++) {
            int col = WN + ni * 8 + t4 * 2;
            float b0 = bvec[col] * bscale, b1 = bvec[col + 1] * bscale;
            float* a = acc[mi][ni];
            if (EPI == 1) {
                epi[r0 * EPITCH + col]           = fmaxf(a[0] + b0, 0.f);
                epi[r0 * EPITCH + col + 1]       = fmaxf(a[1] + b1, 0.f);
                epi[(r0 + 8) * EPITCH + col]     = fmaxf(a[2] + b0, 0.f);
                epi[(r0 + 8) * EPITCH + col + 1] = fmaxf(a[3] + b1, 0.f);
            } else {
                epi[r0 * EPITCH + col]           = (a[0] + b0) * gate0;
                epi[r0 * EPITCH + col + 1]       = (a[1] + b1) * gate0;
                epi[(r0 + 8) * EPITCH + col]     = (a[2] + b0) * gate8;
                epi[(r0 + 8) * EPITCH + col + 1] = (a[3] + b1) * gate8;
            }
        }
    }
    __syncthreads();

    if (EPI == 1) {
        f16* Hp = g_H + (size_t)(rowbase + m0) * F + n0;
        #pragma unroll
        for (int i = 0; i < 32; i++) {
            int c = tid + i * 128;
            int row = c >> 5, q = c & 31;
            float4 v = *(float4*)&epi[row * EPITCH + q * 4];
            f16 h[4];
            h[0] = __float2half_rn(v.x);
            h[1] = __float2half_rn(v.y);
            h[2] = __float2half_rn(v.z);
            h[3] = __float2half_rn(v.w);
            *(uint2*)&Hp[(size_t)row * F + q * 4] = *(uint2*)h;
        }
    } else {
        #pragma unroll
        for (int i = 0; i < 32; i++) {
            int c = tid + i * 128;
            int row = c >> 5, q = c & 31;
            if (m0 + row < cnt) {
                int tok = g_list[e * T_TOK + m0 + row];
                float4 v = *(float4*)&epi[row * EPITCH + q * 4];
                float* op = out + (size_t)tok * D + n0 + q * 4;
                atomicAdd(op + 0, v.x);
                atomicAdd(op + 1, v.y);
                atomicAdd(op + 2, v.z);
                atomicAdd(op + 3, v.w);
            }
        }
    }
}

#define SPLITK2 3

extern "C" void kernel_launch(void* const* d_in, const int* in_sizes, int n_in,
                              void* d_out, int out_size) {
    const float* x     = (const float*)d_in[0];
    const float* noise = (const float*)d_in[1];
    const float* Wg    = (const float*)d_in[2];
    const float* bg    = (const float*)d_in[3];
    const float* Wn    = (const float*)d_in[4];
    const float* bn    = (const float*)d_in[5];
    const float* W1    = (const float*)d_in[6];
    const float* b1    = (const float*)d_in[7];
    const float* W2    = (const float*)d_in[8];
    const float* b2    = (const float*)d_in[9];
    float* out = (float*)d_out;

    static cudaStream_t s2 = nullptr;
    static cudaEvent_t evFork = nullptr, evW1 = nullptr, evW2 = nullptr;
    static bool init_done = false;
    if (!init_done) {
        cudaFuncSetAttribute(moe_gemm_mma<D, F, 1, 1>, cudaFuncAttributeMaxDynamicSharedMemorySize, SMEM_G);
        cudaFuncSetAttribute(moe_gemm_mma<F, D, 2, SPLITK2>, cudaFuncAttributeMaxDynamicSharedMemorySize, SMEM_G);
        cudaStreamCreateWithFlags(&s2, cudaStreamNonBlocking);
        cudaEventCreateWithFlags(&evFork, cudaEventDisableTiming);
        cudaEventCreateWithFlags(&evW1, cudaEventDisableTiming);
        cudaEventCreateWithFlags(&evW2, cudaEventDisableTiming);
        init_done = true;
    }

    // fork: weight conversions on s2, concurrent with router/gather chain
    cudaEventRecord(evFork, 0);
    cudaStreamWaitEvent(s2, evFork, 0);
    conv_weights_kernel<<<4096, 256, 0, s2>>>(W1, 0);
    cudaEventRecord(evW1, s2);
    conv_weights_kernel<<<4096, 256, 0, s2>>>(W2, 1);
    cudaEventRecord(evW2, s2);

    // main stream: routing + gather
    cudaMemsetAsync(out, 0, (size_t)out_size * sizeof(float));
    init_kernel<<<1, 32>>>();
    router_kernel<<<T_TOK / 8, 256>>>(x, noise, Wg, bg, Wn, bn);
    finalize_kernel<<<1, 32>>>();
    gather_kernel<<<dim3(E, 256), 256>>>(x);

    // join W1 before GEMM1, W2 before GEMM2
    cudaStreamWaitEvent(0, evW1, 0);
    moe_gemm_mma<D, F, 1, 1><<<dim3(F / 128, T_TOK / 128, E), 128, SMEM_G>>>(b1, out);
    cudaStreamWaitEvent(0, evW2, 0);
    moe_gemm_mma<F, D, 2, SPLITK2><<<dim3((D / 128) * SPLITK2, T_TOK / 128, E), 128, SMEM_G>>>(b2, out);
}

// round 13
// speedup vs baseline: 1.0391x; 1.0391x over previous
#include <cuda_runtime.h>
#include <cuda_fp16.h>
#include <math.h>
#include <stdint.h>

#define D 768
#define E 8
#define F 3072
#define T_TOK 4096
#define MAXROWS 10240

typedef __half f16;

__device__ int   g_counts[E];
__device__ int   g_off[E + 1];
__device__ int   g_list[E * T_TOK];
__device__ float g_gates[E * T_TOK];
__device__ f16   g_A[(size_t)MAXROWS * D];
__device__ f16   g_H[(size_t)MAXROWS * F];
__device__ f16   g_W1[(size_t)E * D * F];   // [E][D][F] native [k][n], fp16
__device__ f16   g_W2[(size_t)E * D * F];   // [E][F][D] native [k][n], fp16

__device__ __forceinline__ uint32_t smem_u32(const void* p) {
    uint32_t a;
    asm("{ .reg .u64 t; cvta.to.shared.u64 t, %1; cvt.u32.u64 %0, t; }" : "=r"(a) : "l"(p));
    return a;
}
__device__ __forceinline__ void cp16(uint32_t dst, const void* src) {
    asm volatile("cp.async.cg.shared.global [%0], [%1], 16;"
                 :: "r"(dst), "l"(__cvta_generic_to_global(src)));
}
#define CP_COMMIT() asm volatile("cp.async.commit_group;" ::: "memory")

__device__ __forceinline__ void ldm_x4(uint32_t* r, uint32_t addr) {
    asm volatile("ldmatrix.sync.aligned.m8n8.x4.shared.b16 {%0,%1,%2,%3}, [%4];"
                 : "=r"(r[0]), "=r"(r[1]), "=r"(r[2]), "=r"(r[3]) : "r"(addr));
}
__device__ __forceinline__ void ldm_x4_t(uint32_t* r, uint32_t addr) {
    asm volatile("ldmatrix.sync.aligned.m8n8.x4.trans.shared.b16 {%0,%1,%2,%3}, [%4];"
                 : "=r"(r[0]), "=r"(r[1]), "=r"(r[2]), "=r"(r[3]) : "r"(addr));
}
__device__ __forceinline__ void mma_f16(float* c, const uint32_t* a, uint32_t b0, uint32_t b1) {
    asm volatile("mma.sync.aligned.m16n8k16.row.col.f32.f16.f16.f32 "
                 "{%0,%1,%2,%3}, {%4,%5,%6,%7}, {%8,%9}, {%0,%1,%2,%3};"
                 : "+f"(c[0]), "+f"(c[1]), "+f"(c[2]), "+f"(c[3])
                 : "r"(a[0]), "r"(a[1]), "r"(a[2]), "r"(a[3]), "r"(b0), "r"(b1));
}

__global__ void init_kernel() { if (threadIdx.x < E) g_counts[threadIdx.x] = 0; }

// warp-per-token router: 8 tokens per 256-thread block, Wg/Wn staged transposed in smem.
#define WPITCH 776
__global__ void __launch_bounds__(256) router_kernel(
        const float* __restrict__ x, const float* __restrict__ noise,
        const float* __restrict__ Wg, const float* __restrict__ bg,
        const float* __restrict__ Wn, const float* __restrict__ bn) {
    __shared__ float wg[E * WPITCH];
    __shared__ float wn[E * WPITCH];
    int tid = threadIdx.x, lane = tid & 31, w = tid >> 5;
    for (int i = tid; i < D * E; i += 256) {
        int d = i >> 3, e = i & 7;
        wg[e * WPITCH + d] = Wg[i];
        wn[e * WPITCH + d] = Wn[i];
    }
    __syncthreads();

    int t = blockIdx.x * 8 + w;
    const float* xr = x + (size_t)t * D;
    float xv[D / 32];
    #pragma unroll
    for (int i = 0; i < D / 32; i++) xv[i] = xr[i * 32 + lane];

    float sg[E], sn[E];
    #pragma unroll
    for (int e = 0; e < E; e++) { sg[e] = 0.f; sn[e] = 0.f; }
    #pragma unroll
    for (int i = 0; i < D / 32; i++) {
        int d = i * 32 + lane;
        #pragma unroll
        for (int e = 0; e < E; e++) {
            sg[e] = fmaf(xv[i], wg[e * WPITCH + d], sg[e]);
            sn[e] = fmaf(xv[i], wn[e * WPITCH + d], sn[e]);
        }
    }
    #pragma unroll
    for (int e = 0; e < E; e++) {
        #pragma unroll
        for (int o = 16; o > 0; o >>= 1) {
            sg[e] += __shfl_xor_sync(~0u, sg[e], o);
            sn[e] += __shfl_xor_sync(~0u, sn[e], o);
        }
    }
    if (lane == 0) {
        float noisy[E];
        #pragma unroll
        for (int e = 0; e < E; e++) {
            float lg = sg[e] + bg[e], ln = sn[e] + bn[e];
            float sp = (ln > 20.f) ? ln : log1pf(expf(ln));
            noisy[e] = lg + noise[(size_t)t * E + e] * sp;
        }
        int i1 = 0; float v1 = noisy[0];
        #pragma unroll
        for (int e = 1; e < E; e++) if (noisy[e] > v1) { v1 = noisy[e]; i1 = e; }
        int i2 = -1; float v2 = -3.4e38f;
        #pragma unroll
        for (int e = 0; e < E; e++) {
            if (e == i1) continue;
            if (noisy[e] > v2) { v2 = noisy[e]; i2 = e; }
        }
        float eb = expf(v2 - v1);
        float p1 = 1.f / (1.f + eb), p2 = eb / (1.f + eb);
        if (p1 > 1e-9f) {
            int pos = atomicAdd(&g_counts[i1], 1);
            g_list[i1 * T_TOK + pos] = t; g_gates[i1 * T_TOK + pos] = p1;
        }
        if (p2 > 1e-9f) {
            int pos = atomicAdd(&g_counts[i2], 1);
            g_list[i2 * T_TOK + pos] = t; g_gates[i2 * T_TOK + pos] = p2;
        }
    }
}

__global__ void finalize_kernel() {
    if (threadIdx.x == 0) {
        int off = 0;
        for (int e = 0; e < E; e++) { g_off[e] = off; off += (g_counts[e] + 127) & ~127; }
        g_off[E] = off;
    }
}

__global__ void __launch_bounds__(256) gather_kernel(const float* __restrict__ x) {
    int e = blockIdx.x;
    int cnt = g_counts[e], pad = (cnt + 127) & ~127;
    int rb = blockIdx.y * 16;
    if (rb >= pad) return;
    int base = g_off[e];
    const int Q = D / 4;
    for (int idx = threadIdx.x; idx < 16 * Q; idx += 256) {
        int m = rb + idx / Q, q = idx % Q;
        float4 v = make_float4(0.f, 0.f, 0.f, 0.f);
        if (m < cnt)
            v = *(const float4*)&x[(size_t)g_list[e * T_TOK + m] * D + q * 4];
        f16 h[4];
        h[0] = __float2half_rn(v.x);
        h[1] = __float2half_rn(v.y);
        h[2] = __float2half_rn(v.z);
        h[3] = __float2half_rn(v.w);
        *(uint2*)&g_A[(size_t)(base + m) * D + q * 4] = *(uint2*)h;
    }
}

__global__ void __launch_bounds__(256) conv_weights_kernel(const float* __restrict__ W, int which) {
    f16* Th = which ? g_W2 : g_W1;
    const size_t n4 = (size_t)E * D * F / 4;
    size_t stride = (size_t)gridDim.x * blockDim.x;
    for (size_t i = (size_t)blockIdx.x * blockDim.x + threadIdx.x; i < n4; i += stride) {
        float4 v = *(const float4*)&W[i * 4];
        f16 h[4];
        h[0] = __float2half_rn(v.x);
        h[1] = __float2half_rn(v.y);
        h[2] = __float2half_rn(v.z);
        h[3] = __float2half_rn(v.w);
        *(uint2*)&Th[i * 4] = *(uint2*)h;
    }
}

// ------------- pure fp16 mma.sync GEMM, optional split-K -------------
// CTA 128 x 128, K-step 64, 3 smem stages, 8 warps (4M x 2N, warp 32x64), 2 CTAs/SM.
// Mainloop: g-major MMA order with in-place bh reload + double-buffered ah
// (register-frugal software pipeline; bh slack = 12 MMAs, ah slack = full k16).
#define A_PITCH 144
#define A_ARR   18432
#define B_PITCH 272
#define B_ARR   17408
#define STG     35840
#define SMEM_G  107520    // 3 stages

template<int KTOT, int NTOT, int EPI, int SPLITK>
__global__ void __launch_bounds__(256, 2) moe_gemm_mma(const float* __restrict__ bias,
                                                       float* __restrict__ out) {
    constexpr int KLOC = KTOT / SPLITK;
    constexpr int NK   = KLOC / 64;

    int e = blockIdx.z, cnt = g_counts[e];
    int m0 = blockIdx.y * 128;
    int pad = (cnt + 127) & ~127;
    if (m0 >= pad) return;
    int nt = blockIdx.x / SPLITK;
    int ks = blockIdx.x % SPLITK;
    int n0 = nt * 128, rowbase = g_off[e];
    int kbase = ks * KLOC;

    extern __shared__ __align__(1024) char smem[];
    uint32_t sb0 = smem_u32(smem);
    int tid = threadIdx.x, wid = tid >> 5, lane = tid & 31;
    int WM = (wid >> 1) * 32;
    int WN = (wid & 1) * 64;

    const f16* Ag = (EPI == 1 ? g_A : g_H) + (size_t)(rowbase + m0) * KTOT + kbase;
    const f16* Bg = (EPI == 1 ? g_W1 : g_W2) + (size_t)e * D * F + (size_t)kbase * NTOT + n0;

    auto load_stage = [&](int s, int k0) {
        uint32_t sb = sb0 + s * STG;
        #pragma unroll
        for (int i = 0; i < 8; i++) {
            int c = tid + i * 256;
            if (c < 1024) {
                int row = c >> 3, ch = c & 7;
                cp16(sb + row * A_PITCH + ch * 16,
                     Ag + (size_t)row * KTOT + k0 + ch * 8);
            } else {
                int cb = c - 1024, row = cb >> 4, ch = cb & 15;
                cp16(sb + A_ARR + row * B_PITCH + ch * 16,
                     Bg + (size_t)(k0 + row) * NTOT + ch * 8);
            }
        }
        CP_COMMIT();
    };

    float acc[2][8][4];
    #pragma unroll
    for (int mi = 0; mi < 2; mi++)
        #pragma unroll
        for (int ni = 0; ni < 8; ni++)
            #pragma unroll
            for (int q = 0; q < 4; q++) acc[mi][ni][q] = 0.f;

    uint32_t a_off = (uint32_t)((lane & 15) * A_PITCH + (lane >> 4) * 16);
    uint32_t b_off = (uint32_t)((lane & 15) * B_PITCH + (lane >> 4) * 16);

    load_stage(0, 0);
    load_stage(1, 64);

    for (int it = 0; it < NK; it++) {
        int s = it % 3;
        if (it + 1 < NK) asm volatile("cp.async.wait_group 1;" ::: "memory");
        else             asm volatile("cp.async.wait_group 0;" ::: "memory");
        __syncthreads();
        if (it + 2 < NK) load_stage((it + 2) % 3, (it + 2) * 64);

        uint32_t sA = sb0 + s * STG;
        uint32_t sB = sA + A_ARR;

        // preload fragments for k16 = 0
        uint32_t ah[2][2][4], bh[4][4];
        ldm_x4(ah[0][0], sA + WM * A_PITCH + a_off);
        ldm_x4(ah[0][1], sA + (WM + 16) * A_PITCH + a_off);
        #pragma unroll
        for (int g = 0; g < 4; g++)
            ldm_x4_t(bh[g], sB + (WN + g * 16) * 2 + b_off);

        #pragma unroll
        for (int k16 = 0; k16 < 4; k16++) {
            int cur = k16 & 1;
            #pragma unroll
            for (int g = 0; g < 4; g++) {
                mma_f16(acc[0][2 * g],     ah[cur][0], bh[g][0], bh[g][1]);
                mma_f16(acc[0][2 * g + 1], ah[cur][0], bh[g][2], bh[g][3]);
                mma_f16(acc[1][2 * g],     ah[cur][1], bh[g][0], bh[g][1]);
                mma_f16(acc[1][2 * g + 1], ah[cur][1], bh[g][2], bh[g][3]);
                if (k16 < 3)   // bh[g] now dead: reload in place for k16+1
                    ldm_x4_t(bh[g], sB + (k16 + 1) * 16 * B_PITCH + (WN + g * 16) * 2 + b_off);
            }
            if (k16 < 3) {     // ah double-buffered: load k16+1 while k16 in flight
                ldm_x4(ah[cur ^ 1][0], sA + WM * A_PITCH + (k16 + 1) * 32 + a_off);
                ldm_x4(ah[cur ^ 1][1], sA + (WM + 16) * A_PITCH + (k16 + 1) * 32 + a_off);
            }
        }
    }
    __syncthreads();

    // ---- epilogue via smem staging ----
    constexpr int EPITCH = 132;
    float* epi = (float*)smem;
    const float* bvec = bias + (size_t)e * NTOT + n0;
    float bscale = (ks == 0) ? 1.f : 0.f;
    int g4 = lane >> 2, t4 = lane & 3;
    #pragma unroll
    for (int mi = 0; mi < 2; mi++) {
        int r0 = WM + mi * 16 + g4;
        float gate0 = 0.f, gate8 = 0.f;
        if (EPI == 2) {
            if (m0 + r0 < cnt)     gate0 = g_gates[e * T_TOK + m0 + r0];
            if (m0 + r0 + 8 < cnt) gate8 = g_gates[e * T_TOK + m0 + r0 + 8];
        }
        #pragma unroll
        for (int ni = 0; ni < 8; ni++) {
            int col = WN + ni * 8 + t4 * 2;
            float b0 = bvec[col] * bscale, b1 = bvec[col + 1] * bscale;
            float* a = acc[mi][ni];
            if (EPI == 1) {
                epi[r0 * EPITCH + col]           = fmaxf(a[0] + b0, 0.f);
                epi[r0 * EPITCH + col + 1]       = fmaxf(a[1] + b1, 0.f);
                epi[(r0 + 8) * EPITCH + col]     = fmaxf(a[2] + b0, 0.f);
                epi[(r0 + 8) * EPITCH + col + 1] = fmaxf(a[3] + b1, 0.f);
            } else {
                epi[r0 * EPITCH + col]           = (a[0] + b0) * gate0;
                epi[r0 * EPITCH + col + 1]       = (a[1] + b1) * gate0;
                epi[(r0 + 8) * EPITCH + col]     = (a[2] + b0) * gate8;
                epi[(r0 + 8) * EPITCH + col + 1] = (a[3] + b1) * gate8;
            }
        }
    }
    __syncthreads();

    if (EPI == 1) {
        f16* Hp = g_H + (size_t)(rowbase + m0) * F + n0;
        #pragma unroll
        for (int i = 0; i < 16; i++) {
            int c = tid + i * 256;
            int row = c >> 5, q = c & 31;
            float4 v = *(float4*)&epi[row * EPITCH + q * 4];
            f16 h[4];
            h[0] = __float2half_rn(v.x);
            h[1] = __float2half_rn(v.y);
            h[2] = __float2half_rn(v.z);
            h[3] = __float2half_rn(v.w);
            *(uint2*)&Hp[(size_t)row * F + q * 4] = *(uint2*)h;
        }
    } else {
        #pragma unroll
        for (int i = 0; i < 16; i++) {
            int c = tid + i * 256;
            int row = c >> 5, q = c & 31;
            if (m0 + row < cnt) {
                int tok = g_list[e * T_TOK + m0 + row];
                float4 v = *(float4*)&epi[row * EPITCH + q * 4];
                float* op = out + (size_t)tok * D + n0 + q * 4;
                atomicAdd(op + 0, v.x);
                atomicAdd(op + 1, v.y);
                atomicAdd(op + 2, v.z);
                atomicAdd(op + 3, v.w);
            }
        }
    }
}

#define SPLITK2 3

extern "C" void kernel_launch(void* const* d_in, const int* in_sizes, int n_in,
                              void* d_out, int out_size) {
    const float* x     = (const float*)d_in[0];
    const float* noise = (const float*)d_in[1];
    const float* Wg    = (const float*)d_in[2];
    const float* bg    = (const float*)d_in[3];
    const float* Wn    = (const float*)d_in[4];
    const float* bn    = (const float*)d_in[5];
    const float* W1    = (const float*)d_in[6];
    const float* b1    = (const float*)d_in[7];
    const float* W2    = (const float*)d_in[8];
    const float* b2    = (const float*)d_in[9];
    float* out = (float*)d_out;

    static cudaStream_t s2 = nullptr;
    static cudaEvent_t evFork = nullptr, evW1 = nullptr, evW2 = nullptr;
    static bool init_done = false;
    if (!init_done) {
        cudaFuncSetAttribute(moe_gemm_mma<D, F, 1, 1>, cudaFuncAttributeMaxDynamicSharedMemorySize, SMEM_G);
        cudaFuncSetAttribute(moe_gemm_mma<F, D, 2, SPLITK2>, cudaFuncAttributeMaxDynamicSharedMemorySize, SMEM_G);
        cudaStreamCreateWithFlags(&s2, cudaStreamNonBlocking);
        cudaEventCreateWithFlags(&evFork, cudaEventDisableTiming);
        cudaEventCreateWithFlags(&evW1, cudaEventDisableTiming);
        cudaEventCreateWithFlags(&evW2, cudaEventDisableTiming);
        init_done = true;
    }

    // fork: weight conversions on s2, concurrent with router/gather chain
    cudaEventRecord(evFork, 0);
    cudaStreamWaitEvent(s2, evFork, 0);
    conv_weights_kernel<<<4096, 256, 0, s2>>>(W1, 0);
    cudaEventRecord(evW1, s2);
    conv_weights_kernel<<<4096, 256, 0, s2>>>(W2, 1);
    cudaEventRecord(evW2, s2);

    // main stream: routing + gather
    cudaMemsetAsync(out, 0, (size_t)out_size * sizeof(float));
    init_kernel<<<1, 32>>>();
    router_kernel<<<T_TOK / 8, 256>>>(x, noise, Wg, bg, Wn, bn);
    finalize_kernel<<<1, 32>>>();
    gather_kernel<<<dim3(E, 256), 256>>>(x);

    // join W1 before GEMM1, W2 before GEMM2
    cudaStreamWaitEvent(0, evW1, 0);
    moe_gemm_mma<D, F, 1, 1><<<dim3(F / 128, T_TOK / 128, E), 256, SMEM_G>>>(b1, out);
    cudaStreamWaitEvent(0, evW2, 0);
    moe_gemm_mma<F, D, 2, SPLITK2><<<dim3((D / 128) * SPLITK2, T_TOK / 128, E), 256, SMEM_G>>>(b2, out);
}

// round 14
// speedup vs baseline: 1.0525x; 1.0129x over previous
#include <cuda_runtime.h>
#include <cuda_fp16.h>
#include <math.h>
#include <stdint.h>

#define D 768
#define E 8
#define F 3072
#define T_TOK 4096
#define MAXROWS 10240

typedef __half f16;

__device__ int   g_counts[E];
__device__ int   g_off[E + 1];
__device__ int   g_list[E * T_TOK];
__device__ float g_gates[E * T_TOK];
__device__ f16   g_A[(size_t)MAXROWS * D];
__device__ f16   g_H[(size_t)MAXROWS * F];
__device__ f16   g_W1[(size_t)E * D * F];   // [E][D][F] native [k][n], fp16
__device__ f16   g_W2[(size_t)E * D * F];   // [E][F][D] native [k][n], fp16

__device__ __forceinline__ uint32_t smem_u32(const void* p) {
    uint32_t a;
    asm("{ .reg .u64 t; cvta.to.shared.u64 t, %1; cvt.u32.u64 %0, t; }" : "=r"(a) : "l"(p));
    return a;
}
__device__ __forceinline__ void cp16(uint32_t dst, const void* src) {
    asm volatile("cp.async.cg.shared.global [%0], [%1], 16;"
                 :: "r"(dst), "l"(__cvta_generic_to_global(src)));
}
#define CP_COMMIT() asm volatile("cp.async.commit_group;" ::: "memory")

__device__ __forceinline__ void ldm_x4(uint32_t* r, uint32_t addr) {
    asm volatile("ldmatrix.sync.aligned.m8n8.x4.shared.b16 {%0,%1,%2,%3}, [%4];"
                 : "=r"(r[0]), "=r"(r[1]), "=r"(r[2]), "=r"(r[3]) : "r"(addr));
}
__device__ __forceinline__ void ldm_x4_t(uint32_t* r, uint32_t addr) {
    asm volatile("ldmatrix.sync.aligned.m8n8.x4.trans.shared.b16 {%0,%1,%2,%3}, [%4];"
                 : "=r"(r[0]), "=r"(r[1]), "=r"(r[2]), "=r"(r[3]) : "r"(addr));
}
__device__ __forceinline__ void mma_f16(float* c, const uint32_t* a, uint32_t b0, uint32_t b1) {
    asm volatile("mma.sync.aligned.m16n8k16.row.col.f32.f16.f16.f32 "
                 "{%0,%1,%2,%3}, {%4,%5,%6,%7}, {%8,%9}, {%0,%1,%2,%3};"
                 : "+f"(c[0]), "+f"(c[1]), "+f"(c[2]), "+f"(c[3])
                 : "r"(a[0]), "r"(a[1]), "r"(a[2]), "r"(a[3]), "r"(b0), "r"(b1));
}

__global__ void init_kernel() { if (threadIdx.x < E) g_counts[threadIdx.x] = 0; }

// warp-per-token router: 16 tokens per 512-thread block, Wg/Wn staged transposed in smem.
#define WPITCH 776
__global__ void __launch_bounds__(512) router_kernel(
        const float* __restrict__ x, const float* __restrict__ noise,
        const float* __restrict__ Wg, const float* __restrict__ bg,
        const float* __restrict__ Wn, const float* __restrict__ bn) {
    __shared__ float wg[E * WPITCH];
    __shared__ float wn[E * WPITCH];
    int tid = threadIdx.x, lane = tid & 31, w = tid >> 5;
    for (int i = tid; i < D * E; i += 512) {
        int d = i >> 3, e = i & 7;
        wg[e * WPITCH + d] = Wg[i];
        wn[e * WPITCH + d] = Wn[i];
    }
    __syncthreads();

    int t = blockIdx.x * 16 + w;
    const float* xr = x + (size_t)t * D;
    float xv[D / 32];
    #pragma unroll
    for (int i = 0; i < D / 32; i++) xv[i] = xr[i * 32 + lane];

    float sg[E], sn[E];
    #pragma unroll
    for (int e = 0; e < E; e++) { sg[e] = 0.f; sn[e] = 0.f; }
    #pragma unroll
    for (int i = 0; i < D / 32; i++) {
        int d = i * 32 + lane;
        #pragma unroll
        for (int e = 0; e < E; e++) {
            sg[e] = fmaf(xv[i], wg[e * WPITCH + d], sg[e]);
            sn[e] = fmaf(xv[i], wn[e * WPITCH + d], sn[e]);
        }
    }
    #pragma unroll
    for (int e = 0; e < E; e++) {
        #pragma unroll
        for (int o = 16; o > 0; o >>= 1) {
            sg[e] += __shfl_xor_sync(~0u, sg[e], o);
            sn[e] += __shfl_xor_sync(~0u, sn[e], o);
        }
    }
    if (lane == 0) {
        float noisy[E];
        #pragma unroll
        for (int e = 0; e < E; e++) {
            float lg = sg[e] + bg[e], ln = sn[e] + bn[e];
            float sp = (ln > 20.f) ? ln : log1pf(expf(ln));
            noisy[e] = lg + noise[(size_t)t * E + e] * sp;
        }
        int i1 = 0; float v1 = noisy[0];
        #pragma unroll
        for (int e = 1; e < E; e++) if (noisy[e] > v1) { v1 = noisy[e]; i1 = e; }
        int i2 = -1; float v2 = -3.4e38f;
        #pragma unroll
        for (int e = 0; e < E; e++) {
            if (e == i1) continue;
            if (noisy[e] > v2) { v2 = noisy[e]; i2 = e; }
        }
        float eb = expf(v2 - v1);
        float p1 = 1.f / (1.f + eb), p2 = eb / (1.f + eb);
        if (p1 > 1e-9f) {
            int pos = atomicAdd(&g_counts[i1], 1);
            g_list[i1 * T_TOK + pos] = t; g_gates[i1 * T_TOK + pos] = p1;
        }
        if (p2 > 1e-9f) {
            int pos = atomicAdd(&g_counts[i2], 1);
            g_list[i2 * T_TOK + pos] = t; g_gates[i2 * T_TOK + pos] = p2;
        }
    }
}

__global__ void finalize_kernel() {
    if (threadIdx.x == 0) {
        int off = 0;
        for (int e = 0; e < E; e++) { g_off[e] = off; off += (g_counts[e] + 127) & ~127; }
        g_off[E] = off;
    }
}

__global__ void __launch_bounds__(256) gather_kernel(const float* __restrict__ x) {
    int e = blockIdx.x;
    int cnt = g_counts[e], pad = (cnt + 127) & ~127;
    int rb = blockIdx.y * 16;
    if (rb >= pad) return;
    int base = g_off[e];
    const int Q = D / 4;
    for (int idx = threadIdx.x; idx < 16 * Q; idx += 256) {
        int m = rb + idx / Q, q = idx % Q;
        float4 v = make_float4(0.f, 0.f, 0.f, 0.f);
        if (m < cnt)
            v = *(const float4*)&x[(size_t)g_list[e * T_TOK + m] * D + q * 4];
        f16 h[4];
        h[0] = __float2half_rn(v.x);
        h[1] = __float2half_rn(v.y);
        h[2] = __float2half_rn(v.z);
        h[3] = __float2half_rn(v.w);
        *(uint2*)&g_A[(size_t)(base + m) * D + q * 4] = *(uint2*)h;
    }
}

__global__ void __launch_bounds__(256) conv_weights_kernel(const float* __restrict__ W, int which) {
    f16* Th = which ? g_W2 : g_W1;
    const size_t n4 = (size_t)E * D * F / 4;
    size_t stride = (size_t)gridDim.x * blockDim.x;
    for (size_t i = (size_t)blockIdx.x * blockDim.x + threadIdx.x; i < n4; i += stride) {
        float4 v = *(const float4*)&W[i * 4];
        f16 h[4];
        h[0] = __float2half_rn(v.x);
        h[1] = __float2half_rn(v.y);
        h[2] = __float2half_rn(v.z);
        h[3] = __float2half_rn(v.w);
        *(uint2*)&Th[i * 4] = *(uint2*)h;
    }
}

// ------------- pure fp16 mma.sync GEMM, optional split-K -------------
// CTA 128 x 128, K-step 64, 3 smem stages, 8 warps (4M x 2N, warp 32x64), 2 CTAs/SM.
#define A_PITCH 144
#define A_ARR   18432
#define B_PITCH 272
#define B_ARR   17408
#define STG     35840
#define SMEM_G  107520    // 3 stages

template<int KTOT, int NTOT, int EPI, int SPLITK>
__global__ void __launch_bounds__(256, 2) moe_gemm_mma(const float* __restrict__ bias,
                                                       float* __restrict__ out) {
    constexpr int KLOC = KTOT / SPLITK;
    constexpr int NK   = KLOC / 64;

    int e = blockIdx.z, cnt = g_counts[e];
    int m0 = blockIdx.y * 128;
    int pad = (cnt + 127) & ~127;
    if (m0 >= pad) return;
    int nt = blockIdx.x / SPLITK;
    int ks = blockIdx.x % SPLITK;
    int n0 = nt * 128, rowbase = g_off[e];
    int kbase = ks * KLOC;

    extern __shared__ __align__(1024) char smem[];
    uint32_t sb0 = smem_u32(smem);
    int tid = threadIdx.x, wid = tid >> 5, lane = tid & 31;
    int WM = (wid >> 1) * 32;
    int WN = (wid & 1) * 64;

    const f16* Ag = (EPI == 1 ? g_A : g_H) + (size_t)(rowbase + m0) * KTOT + kbase;
    const f16* Bg = (EPI == 1 ? g_W1 : g_W2) + (size_t)e * D * F + (size_t)kbase * NTOT + n0;

    auto load_stage = [&](int s, int k0) {
        uint32_t sb = sb0 + s * STG;
        #pragma unroll
        for (int i = 0; i < 8; i++) {
            int c = tid + i * 256;
            if (c < 1024) {
                int row = c >> 3, ch = c & 7;
                cp16(sb + row * A_PITCH + ch * 16,
                     Ag + (size_t)row * KTOT + k0 + ch * 8);
            } else {
                int cb = c - 1024, row = cb >> 4, ch = cb & 15;
                cp16(sb + A_ARR + row * B_PITCH + ch * 16,
                     Bg + (size_t)(k0 + row) * NTOT + ch * 8);
            }
        }
        CP_COMMIT();
    };

    float acc[2][8][4];
    #pragma unroll
    for (int mi = 0; mi < 2; mi++)
        #pragma unroll
        for (int ni = 0; ni < 8; ni++)
            #pragma unroll
            for (int q = 0; q < 4; q++) acc[mi][ni][q] = 0.f;

    uint32_t a_off = (uint32_t)((lane & 15) * A_PITCH + (lane >> 4) * 16);
    uint32_t b_off = (uint32_t)((lane & 15) * B_PITCH + (lane >> 4) * 16);

    load_stage(0, 0);
    load_stage(1, 64);

    #pragma unroll 3
    for (int it = 0; it < NK; it++) {
        int s = it % 3;
        if (it + 1 < NK) asm volatile("cp.async.wait_group 1;" ::: "memory");
        else             asm volatile("cp.async.wait_group 0;" ::: "memory");
        __syncthreads();

        uint32_t sA = sb0 + s * STG;
        uint32_t sB = sA + A_ARR;

        // preload fragments for k16 = 0 FIRST, so HMMA starts before the
        // next stage's LDGSTS burst occupies issue slots
        uint32_t ah[2][2][4], bh[4][4];
        ldm_x4(ah[0][0], sA + WM * A_PITCH + a_off);
        ldm_x4(ah[0][1], sA + (WM + 16) * A_PITCH + a_off);
        #pragma unroll
        for (int g = 0; g < 4; g++)
            ldm_x4_t(bh[g], sB + (WN + g * 16) * 2 + b_off);

        if (it + 2 < NK) load_stage((it + 2) % 3, (it + 2) * 64);

        #pragma unroll
        for (int k16 = 0; k16 < 4; k16++) {
            int cur = k16 & 1;
            #pragma unroll
            for (int g = 0; g < 4; g++) {
                mma_f16(acc[0][2 * g],     ah[cur][0], bh[g][0], bh[g][1]);
                mma_f16(acc[0][2 * g + 1], ah[cur][0], bh[g][2], bh[g][3]);
                mma_f16(acc[1][2 * g],     ah[cur][1], bh[g][0], bh[g][1]);
                mma_f16(acc[1][2 * g + 1], ah[cur][1], bh[g][2], bh[g][3]);
                if (k16 < 3)
                    ldm_x4_t(bh[g], sB + (k16 + 1) * 16 * B_PITCH + (WN + g * 16) * 2 + b_off);
            }
            if (k16 < 3) {
                ldm_x4(ah[cur ^ 1][0], sA + WM * A_PITCH + (k16 + 1) * 32 + a_off);
                ldm_x4(ah[cur ^ 1][1], sA + (WM + 16) * A_PITCH + (k16 + 1) * 32 + a_off);
            }
        }
    }
    __syncthreads();

    // ---- epilogue via smem staging ----
    constexpr int EPITCH = 132;
    float* epi = (float*)smem;
    const float* bvec = bias + (size_t)e * NTOT + n0;
    float bscale = (ks == 0) ? 1.f : 0.f;
    int g4 = lane >> 2, t4 = lane & 3;
    #pragma unroll
    for (int mi = 0; mi < 2; mi++) {
        int r0 = WM + mi * 16 + g4;
        float gate0 = 0.f, gate8 = 0.f;
        if (EPI == 2) {
            if (m0 + r0 < cnt)     gate0 = g_gates[e * T_TOK + m0 + r0];
            if (m0 + r0 + 8 < cnt) gate8 = g_gates[e * T_TOK + m0 + r0 + 8];
        }
        #pragma unroll
        for (int ni = 0; ni < 8; ni++) {
            int col = WN + ni * 8 + t4 * 2;
            float b0 = bvec[col] * bscale, b1 = bvec[col + 1] * bscale;
            float* a = acc[mi][ni];
            if (EPI == 1) {
                epi[r0 * EPITCH + col]           = fmaxf(a[0] + b0, 0.f);
                epi[r0 * EPITCH + col + 1]       = fmaxf(a[1] + b1, 0.f);
                epi[(r0 + 8) * EPITCH + col]     = fmaxf(a[2] + b0, 0.f);
                epi[(r0 + 8) * EPITCH + col + 1] = fmaxf(a[3] + b1, 0.f);
            } else {
                epi[r0 * EPITCH + col]           = (a[0] + b0) * gate0;
                epi[r0 * EPITCH + col + 1]       = (a[1] + b1) * gate0;
                epi[(r0 + 8) * EPITCH + col]     = (a[2] + b0) * gate8;
                epi[(r0 + 8) * EPITCH + col + 1] = (a[3] + b1) * gate8;
            }
        }
    }
    __syncthreads();

    if (EPI == 1) {
        f16* Hp = g_H + (size_t)(rowbase + m0) * F + n0;
        #pragma unroll
        for (int i = 0; i < 16; i++) {
            int c = tid + i * 256;
            int row = c >> 5, q = c & 31;
            float4 v = *(float4*)&epi[row * EPITCH + q * 4];
            f16 h[4];
            h[0] = __float2half_rn(v.x);
            h[1] = __float2half_rn(v.y);
            h[2] = __float2half_rn(v.z);
            h[3] = __float2half_rn(v.w);
            *(uint2*)&Hp[(size_t)row * F + q * 4] = *(uint2*)h;
        }
    } else {
        #pragma unroll
        for (int i = 0; i < 16; i++) {
            int c = tid + i * 256;
            int row = c >> 5, q = c & 31;
            if (m0 + row < cnt) {
                int tok = g_list[e * T_TOK + m0 + row];
                float4 v = *(float4*)&epi[row * EPITCH + q * 4];
                float* op = out + (size_t)tok * D + n0 + q * 4;
                atomicAdd(op + 0, v.x);
                atomicAdd(op + 1, v.y);
                atomicAdd(op + 2, v.z);
                atomicAdd(op + 3, v.w);
            }
        }
    }
}

#define SPLITK2 3

extern "C" void kernel_launch(void* const* d_in, const int* in_sizes, int n_in,
                              void* d_out, int out_size) {
    const float* x     = (const float*)d_in[0];
    const float* noise = (const float*)d_in[1];
    const float* Wg    = (const float*)d_in[2];
    const float* bg    = (const float*)d_in[3];
    const float* Wn    = (const float*)d_in[4];
    const float* bn    = (const float*)d_in[5];
    const float* W1    = (const float*)d_in[6];
    const float* b1    = (const float*)d_in[7];
    const float* W2    = (const float*)d_in[8];
    const float* b2    = (const float*)d_in[9];
    float* out = (float*)d_out;

    static cudaStream_t s2 = nullptr;
    static cudaEvent_t evFork = nullptr, evW1 = nullptr, evW2 = nullptr;
    static bool init_done = false;
    if (!init_done) {
        cudaFuncSetAttribute(moe_gemm_mma<D, F, 1, 1>, cudaFuncAttributeMaxDynamicSharedMemorySize, SMEM_G);
        cudaFuncSetAttribute(moe_gemm_mma<F, D, 2, SPLITK2>, cudaFuncAttributeMaxDynamicSharedMemorySize, SMEM_G);
        cudaStreamCreateWithFlags(&s2, cudaStreamNonBlocking);
        cudaEventCreateWithFlags(&evFork, cudaEventDisableTiming);
        cudaEventCreateWithFlags(&evW1, cudaEventDisableTiming);
        cudaEventCreateWithFlags(&evW2, cudaEventDisableTiming);
        init_done = true;
    }

    // init + fork: weight conversions on s2, concurrent with router/gather chain
    init_kernel<<<1, 32>>>();
    cudaEventRecord(evFork, 0);
    cudaStreamWaitEvent(s2, evFork, 0);
    conv_weights_kernel<<<4096, 256, 0, s2>>>(W1, 0);
    cudaEventRecord(evW1, s2);
    conv_weights_kernel<<<4096, 256, 0, s2>>>(W2, 1);
    cudaEventRecord(evW2, s2);

    // main stream: routing + gather
    cudaMemsetAsync(out, 0, (size_t)out_size * sizeof(float));
    router_kernel<<<T_TOK / 16, 512>>>(x, noise, Wg, bg, Wn, bn);
    finalize_kernel<<<1, 32>>>();
    gather_kernel<<<dim3(E, 256), 256>>>(x);

    // join W1 before GEMM1, W2 before GEMM2
    cudaStreamWaitEvent(0, evW1, 0);
    moe_gemm_mma<D, F, 1, 1><<<dim3(F / 128, T_TOK / 128, E), 256, SMEM_G>>>(b1, out);
    cudaStreamWaitEvent(0, evW2, 0);
    moe_gemm_mma<F, D, 2, SPLITK2><<<dim3((D / 128) * SPLITK2, T_TOK / 128, E), 256, SMEM_G>>>(b2, out);
}